// round 17
// baseline (speedup 1.0000x reference)
#include <cuda_runtime.h>

// WindowOverlapProcessor: full-width tiles -> zero j-overlap staging.
// Tile = (b, row-pair, full 512-px row): 126 chunks (2 i-rows x 63 windows)
// x 384B, each window row-pair fetched EXACTLY once (R10 fetched 33 chunks
// per 32 slots -> ~5MB/replay un-deduplicated excess at a hard ~5.45TB/s
// DRAM ceiling). cp.async staging (no clamps needed), conflict-free LDS.128
// (chunk stride 26 f4), compile-time gaussian, consumer-side clamp-index +
// zero-weight for j boundaries. 256 thr, 52.4KB dynamic smem -> 4 blocks/SM
// (32 warps, same as R10). 2048 one-shot blocks.

#define HW_      63
#define NW_      (HW_ * HW_)
#define PLANE    (512 * 512)
#define CHUNK_F4 26
#define BUF_F4   (126 * CHUNK_F4)     // 3276 f4 = 52416 B
#define SMEM_B   (BUF_F4 * 16)

#define G0 0.17242162f
#define G1 0.26705262f
#define G2 0.38855860f
#define G3 0.53109700f
#define G4 0.68194030f
#define G5 0.82257760f
#define G6 0.93210250f
#define G7 0.99221790f
#define EPS2 9.1698556e-7f            // 1e-8 * s^2

__constant__ float GT[16] = { G0, G1, G2, G3, G4, G5, G6, G7,
                              G7, G6, G5, G4, G3, G2, G1, G0 };

__global__ void __launch_bounds__(256, 4)
wop_r17(const float* __restrict__ windows, float* __restrict__ out)
{
    extern __shared__ float4 stage[];          // 52416 B dynamic

    int tid = threadIdx.x;
    int bx  = blockIdx.x;
    int hpair = bx & 255;
    int b     = bx >> 8;
    int h0 = hpair << 1;               // even

    int kh = h0 >> 3;
    int i0cl = max(kh - 1, 0), i1cl = min(kh, HW_ - 1);
    int dA = h0 - (i0cl << 3), dB = h0 - (i1cl << 3);   // even, [0,14]
    int bNW = b * NW_;

    unsigned sb = (unsigned)__cvta_generic_to_shared(stage);

    // ---- staging: 126 chunks x 24 float4 via cp.async, NO clamps ----
    {
        int base0 = (bNW + i0cl * HW_) * 192 + dA * 12;   // f4 units
        int base1 = (bNW + i1cl * HW_) * 192 + dB * 12;

        // i-row 0 -> chunks 0..62 (63*24 = 1512 f4)
        int c = tid / 24, w = tid - c * 24;
        for (int s = tid; s < 1512; s += 256) {
            const float4* src = ((const float4*)windows) + (base0 + c * 192 + w);
            unsigned dst = sb + (unsigned)((c * CHUNK_F4 + w) << 4);
            asm volatile("cp.async.cg.shared.global [%0], [%1], 16;"
                         :: "r"(dst), "l"(src) : "memory");
            w += 16; c += 10; if (w >= 24) { w -= 24; ++c; }
        }
        // i-row 1 -> chunks 63..125
        c = tid / 24; w = tid - c * 24;
        for (int s = tid; s < 1512; s += 256) {
            const float4* src = ((const float4*)windows) + (base1 + c * 192 + w);
            unsigned dst = sb + (unsigned)(((63 + c) * CHUNK_F4 + w) << 4);
            asm volatile("cp.async.cg.shared.global [%0], [%1], 16;"
                         :: "r"(dst), "l"(src) : "memory");
            w += 16; c += 10; if (w >= 24) { w -= 24; ++c; }
        }
        asm volatile("cp.async.commit_group;" ::: "memory");
    }

    // ---- consumer setup (overlaps the copies) ----
    int r   = tid >> 7;                // row 0/1
    int idx = tid & 127;               // px-group within row
    int w4  = idx << 2;
    int h   = h0 + r;
    int kw  = idx >> 1;                // w4 >> 3
    bool selhi = (idx & 1) != 0;       // dwA=12 / dwB=4 when set

    bool vi0 = (kh >= 1),  vi1 = (kh <= HW_ - 1);
    bool vj0 = (kw >= 1),  vj1 = (kw <= HW_ - 1);

    int cA = max(kw - 1, 0);           // window kw-1, clamped
    int cB = min(kw, HW_ - 1);         // window kw, clamped

    float gh0 = vi0 ? GT[(h & 7) + 8] : 0.0f;
    float gh1 = vi1 ? GT[h & 7]       : 0.0f;

    float gwA0 = vj0 ? (selhi ? G3 : G7) : 0.0f;
    float gwA1 = vj0 ? (selhi ? G2 : G6) : 0.0f;
    float gwA2 = vj0 ? (selhi ? G1 : G5) : 0.0f;
    float gwA3 = vj0 ? (selhi ? G0 : G4) : 0.0f;
    float gwB0 = vj1 ? (selhi ? G4 : G0) : 0.0f;
    float gwB1 = vj1 ? (selhi ? G5 : G1) : 0.0f;
    float gwB2 = vj1 ? (selhi ? G6 : G2) : 0.0f;
    float gwB3 = vj1 ? (selhi ? G7 : G3) : 0.0f;

    float sh = gh0 + gh1;
    float inv0 = 1.0f / (sh * (gwA0 + gwB0) + EPS2);
    float inv1 = 1.0f / (sh * (gwA1 + gwB1) + EPS2);
    float inv2 = 1.0f / (sh * (gwA2 + gwB2) + EPS2);
    float inv3 = 1.0f / (sh * (gwA3 + gwB3) + EPS2);

    int rowoff = r * 12;
    int fA = selhi ? 9 : 6;
    int fB = selhi ? 3 : 0;
    int c00 = cA        * CHUNK_F4 + rowoff + fA;   // (kh-1, kw-1)
    int c01 = cB        * CHUNK_F4 + rowoff + fB;   // (kh-1, kw)
    int c10 = (63 + cA) * CHUNK_F4 + rowoff + fA;   // (kh,   kw-1)
    int c11 = (63 + cB) * CHUNK_F4 + rowoff + fB;   // (kh,   kw)

    asm volatile("cp.async.wait_group 0;" ::: "memory");
    __syncthreads();

    float a00, a01, a02, a10, a11, a12, a20, a21, a22, a30, a31, a32;
    // per 3-float4 group: va={p0c0,p0c1,p0c2,p1c0} vb={p1c1,p1c2,p2c0,p2c1}
    //                     vc={p2c2,p3c0,p3c1,p3c2}
    {
        float4 va = stage[c00], vb = stage[c00 + 1], vc = stage[c00 + 2];
        float q0 = gh0 * gwA0, q1 = gh0 * gwA1, q2 = gh0 * gwA2, q3 = gh0 * gwA3;
        a00 = q0 * va.x; a01 = q0 * va.y; a02 = q0 * va.z;
        a10 = q1 * va.w; a11 = q1 * vb.x; a12 = q1 * vb.y;
        a20 = q2 * vb.z; a21 = q2 * vb.w; a22 = q2 * vc.x;
        a30 = q3 * vc.y; a31 = q3 * vc.z; a32 = q3 * vc.w;
    }
    {
        float4 va = stage[c01], vb = stage[c01 + 1], vc = stage[c01 + 2];
        float q0 = gh0 * gwB0, q1 = gh0 * gwB1, q2 = gh0 * gwB2, q3 = gh0 * gwB3;
        a00 += q0 * va.x; a01 += q0 * va.y; a02 += q0 * va.z;
        a10 += q1 * va.w; a11 += q1 * vb.x; a12 += q1 * vb.y;
        a20 += q2 * vb.z; a21 += q2 * vb.w; a22 += q2 * vc.x;
        a30 += q3 * vc.y; a31 += q3 * vc.z; a32 += q3 * vc.w;
    }
    {
        float4 va = stage[c10], vb = stage[c10 + 1], vc = stage[c10 + 2];
        float q0 = gh1 * gwA0, q1 = gh1 * gwA1, q2 = gh1 * gwA2, q3 = gh1 * gwA3;
        a00 += q0 * va.x; a01 += q0 * va.y; a02 += q0 * va.z;
        a10 += q1 * va.w; a11 += q1 * vb.x; a12 += q1 * vb.y;
        a20 += q2 * vb.z; a21 += q2 * vb.w; a22 += q2 * vc.x;
        a30 += q3 * vc.y; a31 += q3 * vc.z; a32 += q3 * vc.w;
    }
    {
        float4 va = stage[c11], vb = stage[c11 + 1], vc = stage[c11 + 2];
        float q0 = gh1 * gwB0, q1 = gh1 * gwB1, q2 = gh1 * gwB2, q3 = gh1 * gwB3;
        a00 += q0 * va.x; a01 += q0 * va.y; a02 += q0 * va.z;
        a10 += q1 * va.w; a11 += q1 * vb.x; a12 += q1 * vb.y;
        a20 += q2 * vb.z; a21 += q2 * vb.w; a22 += q2 * vc.x;
        a30 += q3 * vc.y; a31 += q3 * vc.z; a32 += q3 * vc.w;
    }

    float* ob = out + b * (3 * PLANE) + (h << 9) + w4;
    __stcs((float4*)(ob),
           make_float4(a00 * inv0, a10 * inv1, a20 * inv2, a30 * inv3));
    __stcs((float4*)(ob + PLANE),
           make_float4(a01 * inv0, a11 * inv1, a21 * inv2, a31 * inv3));
    __stcs((float4*)(ob + 2 * PLANE),
           make_float4(a02 * inv0, a12 * inv1, a22 * inv2, a32 * inv3));
}

extern "C" void kernel_launch(void* const* d_in, const int* in_sizes, int n_in,
                              void* d_out, int out_size)
{
    const float* windows = (const float*)d_in[0];
    float* out = (float*)d_out;
    cudaFuncSetAttribute(wop_r17, cudaFuncAttributeMaxDynamicSharedMemorySize, SMEM_B);
    cudaFuncSetAttribute(wop_r17, cudaFuncAttributePreferredSharedMemoryCarveout, 100);
    // 8 b x 256 h-pairs = 2048 one-shot blocks, full-width tiles
    wop_r17<<<2048, 256, SMEM_B>>>(windows, out);
}